// round 14
// baseline (speedup 1.0000x reference)
#include <cuda_runtime.h>
#include <cuda_fp16.h>
#include <string.h>
#include <stdint.h>

#define NN 100000
#define EE 1600000
#define DD 128
#define HH 8
#define CAP 96

typedef unsigned long long ull;

// ---------------- scratch (device globals; no allocations allowed) ----------
__device__ __align__(16) float  g_h[NN * DD];    // hidden state fp32 (residual)
__device__ __align__(16) __half g_hh[NN * DD];   // hidden state fp16 (MMA input)
__device__ __align__(16) __half g_xhh[NN * DD];  // transformed feats fp16
__device__ __align__(16) __half g_es[NN * HH];   // src attn logits (fp16)
__device__ __align__(16) __half g_ed[NN * HH];   // dst attn logits (fp16)
__device__ int   g_cur[NN];                      // bucket fill counts (BSS zero)
__device__ int   g_bkt[NN * CAP];                // incoming-src buckets per dst
__device__ double g_part[1024 * DD];
__device__ __align__(16) __half g_Whin[DD * 256];    // W_in fp16 [n][k]
__device__ __align__(16) __half g_Wh[4 * DD * DD];   // gat_W fp16 [l][n][k]

// single dynamic-smem symbol shared by all kernels
extern __shared__ char dynsmem[];

__device__ __forceinline__ uint32_t smem_u32(const void* p) {
    uint32_t a;
    asm("{ .reg .u64 t; cvta.to.shared.u64 t, %1; cvt.u32.u64 %0, t; }"
        : "=r"(a) : "l"(p));
    return a;
}

// ---------------- prep: weight fp16 convert + bucket scatter -----------------
// blocks 0..383 convert weights; remaining blocks grid-stride the edge list.
// g_cur is zero on entry (BSS initially; reset by pool_partial each replay).
__global__ void prep_kernel(const float* __restrict__ Win,
                            const float* __restrict__ gw,
                            const int* __restrict__ src,
                            const int* __restrict__ dst) {
    int idx = blockIdx.x * blockDim.x + threadIdx.x;
    if (idx < 32768) {
        g_Whin[idx] = __float2half(Win[idx]);       // [n][k] as-is
    } else if (idx < 98304) {
        int r = idx - 32768;
        g_Wh[r] = __float2half(gw[r]);              // [l][n][k] as-is
    } else {
        int stride = gridDim.x * blockDim.x - 98304;
        for (int i = idx - 98304; i < EE; i += stride) {
            int d = dst[i];
            int p = atomicAdd(&g_cur[d], 1);
            if (p < CAP) g_bkt[d * CAP + p] = src[i];
        }
    }
}

// ---------------- unified HMMA GEMM ------------------------------------------
// C[M,128] = A[M,K] @ B^T (B = [128 n][K k] fp16). 128x128 tile per CTA,
// 8 warps in a 4m x 2n grid, warp tile 32x64, mma.m16n8k16 f16->f32,
// K chunked by 128. Per k16-step: 6 LDSM.x4 vs 16 MMA.
#define HS_A 0
#define HS_B 32768
#define HS_AS 65536
#define HS_AD 66048
#define HS_TOT 66560

__device__ __forceinline__ void ldsm_x4(uint32_t& r0, uint32_t& r1,
                                        uint32_t& r2, uint32_t& r3,
                                        uint32_t addr) {
    asm volatile(
        "ldmatrix.sync.aligned.m8n8.x4.shared.b16 {%0,%1,%2,%3}, [%4];"
        : "=r"(r0), "=r"(r1), "=r"(r2), "=r"(r3) : "r"(addr));
}

__device__ __forceinline__ void mma16816(float* c, uint32_t a0, uint32_t a1,
                                         uint32_t a2, uint32_t a3,
                                         uint32_t b0, uint32_t b1) {
    asm volatile(
        "mma.sync.aligned.m16n8k16.row.col.f32.f16.f16.f32 "
        "{%0,%1,%2,%3}, {%4,%5,%6,%7}, {%8,%9}, {%0,%1,%2,%3};"
        : "+f"(c[0]), "+f"(c[1]), "+f"(c[2]), "+f"(c[3])
        : "r"(a0), "r"(a1), "r"(a2), "r"(a3), "r"(b0), "r"(b1));
}

__device__ __forceinline__ uint32_t pack_h2(float a, float b) {
    __half2 h = __floats2half2_rn(a, b);
    uint32_t u;
    memcpy(&u, &h, 4);
    return u;
}

template <int K, bool AFP32, bool ATTN>
__global__ void __launch_bounds__(256, 2)
gemm_hmma_kernel(const void* __restrict__ Asrc, const __half* __restrict__ Bh,
                 const float* __restrict__ bias, float* __restrict__ Cout,
                 const float* __restrict__ asrc, const float* __restrict__ adst) {
    char* smem = dynsmem;
    uint32_t sb = smem_u32(smem);
    int tid = threadIdx.x;
    int lane = tid & 31;
    int wid = tid >> 5;
    long row0 = (long)blockIdx.x * 128;

    int m0 = (wid & 3) * 32;   // warp row origin
    int n0 = (wid >> 2) * 64;  // warp col origin

    float acc[2][8][4];
#pragma unroll
    for (int mi = 0; mi < 2; ++mi)
#pragma unroll
        for (int u = 0; u < 8; ++u)
#pragma unroll
            for (int i = 0; i < 4; ++i) acc[mi][u][i] = 0.f;

    int l15 = lane & 15;
    int khalf = lane >> 4;

    for (int kk = 0; kk < K; kk += 128) {
        if (kk) __syncthreads();
#pragma unroll
        for (int p = 0; p < 8; ++p) {
            int lin = p * 256 + tid;       // 0..2047 chunks
            int r = lin >> 4;              // row 0..127
            int c = lin & 15;              // 16B chunk 0..15
            int swc = c ^ (r & 7);
            long grow = row0 + r;
            uint4 va = make_uint4(0, 0, 0, 0);
            if (grow < NN) {
                if (AFP32) {
                    const float* ax = (const float*)Asrc + grow * K + kk + c * 8;
                    float4 f0 = *(const float4*)ax;
                    float4 f1 = *(const float4*)(ax + 4);
                    va.x = pack_h2(f0.x, f0.y);
                    va.y = pack_h2(f0.z, f0.w);
                    va.z = pack_h2(f1.x, f1.y);
                    va.w = pack_h2(f1.z, f1.w);
                } else {
                    va = *(const uint4*)((const __half*)Asrc + grow * 128 + c * 8);
                }
            }
            *(uint4*)(smem + HS_A + r * 256 + swc * 16) = va;
            uint4 vb = *(const uint4*)&Bh[(long)r * K + kk + c * 8];
            *(uint4*)(smem + HS_B + r * 256 + swc * 16) = vb;
        }
        if (kk == 0 && tid < 128) {
            if (ATTN) {
                ((float*)(smem + HS_AS))[tid] = asrc[tid];
                ((float*)(smem + HS_AD))[tid] = adst[tid];
            }
            if (AFP32) ((float*)(smem + HS_AS))[tid] = bias[tid];
        }
        __syncthreads();

#pragma unroll
        for (int ks = 0; ks < 8; ++ks) {
            int kc = ks * 2 + khalf;
            uint32_t a[2][4];
#pragma unroll
            for (int mi = 0; mi < 2; ++mi) {
                int ar = m0 + mi * 16 + l15;
                ldsm_x4(a[mi][0], a[mi][1], a[mi][2], a[mi][3],
                        sb + HS_A + ar * 256 + (kc ^ (ar & 7)) * 16);
            }
#pragma unroll
            for (int j = 0; j < 4; ++j) {
                int br = n0 + j * 16 + l15;
                uint32_t b0, b1, b2, b3;
                ldsm_x4(b0, b1, b2, b3,
                        sb + HS_B + br * 256 + (kc ^ (br & 7)) * 16);
#pragma unroll
                for (int mi = 0; mi < 2; ++mi) {
                    mma16816(acc[mi][2 * j], a[mi][0], a[mi][1], a[mi][2], a[mi][3], b0, b2);
                    mma16816(acc[mi][2 * j + 1], a[mi][0], a[mi][1], a[mi][2], a[mi][3], b1, b3);
                }
            }
        }
    }

    // epilogue: warp covers rows [m0, m0+32) x cols [n0, n0+64)
    int qr = lane >> 2;
    int qc = (lane & 3) * 2;

#pragma unroll
    for (int mi = 0; mi < 2; ++mi) {
        long glo = row0 + m0 + mi * 16 + qr;
        long ghi = glo + 8;
        bool vlo = (glo < NN), vhi = (ghi < NN);

        if (AFP32) {
            const float* sbias = (const float*)(smem + HS_AS);
#pragma unroll
            for (int u = 0; u < 8; ++u) {
                int col = n0 + u * 8 + qc;
                float b0 = sbias[col], b1 = sbias[col + 1];
                float c0 = acc[mi][u][0] + b0, c1 = acc[mi][u][1] + b1;
                float c2 = acc[mi][u][2] + b0, c3 = acc[mi][u][3] + b1;
                if (vlo) {
                    *(float2*)&Cout[glo * 128 + col] = make_float2(c0, c1);
                    *(__half2*)&g_hh[glo * 128 + col] = __floats2half2_rn(c0, c1);
                }
                if (vhi) {
                    *(float2*)&Cout[ghi * 128 + col] = make_float2(c2, c3);
                    *(__half2*)&g_hh[ghi * 128 + col] = __floats2half2_rn(c2, c3);
                }
            }
        }
        if (ATTN) {
            const float* s_as = (const float*)(smem + HS_AS);
            const float* s_ad = (const float*)(smem + HS_AD);
            float eslo[4], edlo[4], eshi[4], edhi[4];
#pragma unroll
            for (int h = 0; h < 4; ++h) { eslo[h] = edlo[h] = eshi[h] = edhi[h] = 0.f; }
#pragma unroll
            for (int u = 0; u < 8; ++u) {
                int col = n0 + u * 8 + qc;
                int h = u >> 1;
                float c0 = acc[mi][u][0], c1 = acc[mi][u][1];
                float c2 = acc[mi][u][2], c3 = acc[mi][u][3];
                if (vlo) *(__half2*)&g_xhh[glo * 128 + col] = __floats2half2_rn(c0, c1);
                if (vhi) *(__half2*)&g_xhh[ghi * 128 + col] = __floats2half2_rn(c2, c3);
                float as0 = s_as[col], as1 = s_as[col + 1];
                float ad0 = s_ad[col], ad1 = s_ad[col + 1];
                eslo[h] += c0 * as0 + c1 * as1;
                edlo[h] += c0 * ad0 + c1 * ad1;
                eshi[h] += c2 * as0 + c3 * as1;
                edhi[h] += c2 * ad0 + c3 * ad1;
            }
#pragma unroll
            for (int h = 0; h < 4; ++h) {
                eslo[h] += __shfl_xor_sync(0xffffffffu, eslo[h], 1);
                eslo[h] += __shfl_xor_sync(0xffffffffu, eslo[h], 2);
                edlo[h] += __shfl_xor_sync(0xffffffffu, edlo[h], 1);
                edlo[h] += __shfl_xor_sync(0xffffffffu, edlo[h], 2);
                eshi[h] += __shfl_xor_sync(0xffffffffu, eshi[h], 1);
                eshi[h] += __shfl_xor_sync(0xffffffffu, eshi[h], 2);
                edhi[h] += __shfl_xor_sync(0xffffffffu, edhi[h], 1);
                edhi[h] += __shfl_xor_sync(0xffffffffu, edhi[h], 2);
            }
            int hbase = n0 >> 4;   // first head of this warp (0 or 4)
            if ((lane & 3) == 0) {
                if (vlo) {
                    *(uint2*)&g_es[glo * 8 + hbase] =
                        make_uint2(pack_h2(eslo[0], eslo[1]), pack_h2(eslo[2], eslo[3]));
                    *(uint2*)&g_ed[glo * 8 + hbase] =
                        make_uint2(pack_h2(edlo[0], edlo[1]), pack_h2(edlo[2], edlo[3]));
                }
                if (vhi) {
                    *(uint2*)&g_es[ghi * 8 + hbase] =
                        make_uint2(pack_h2(eshi[0], eshi[1]), pack_h2(eshi[2], eshi[3]));
                    *(uint2*)&g_ed[ghi * 8 + hbase] =
                        make_uint2(pack_h2(edhi[0], edhi[1]), pack_h2(edhi[2], edhi[3]));
                }
            }
        }
    }
}

// ---------------- fused aggregate + residual + LayerNorm --------------------
__global__ void __launch_bounds__(256)
aggregate_kernel(const float* __restrict__ gbias, const float* __restrict__ lng,
                 const float* __restrict__ lnb, float* __restrict__ hout,
                 __half* __restrict__ hh) {
    int lane = threadIdx.x & 31;
    int n = blockIdx.x * 8 + (threadIdx.x >> 5);
    int head = lane >> 2;

    float edn = __half2float(g_ed[n * 8 + head]);
    float e0 = __half2float(g_es[n * 8 + head]) + edn;
    e0 = (e0 > 0.f) ? e0 : 0.2f * e0;
    float w0 = __expf(e0);

    float d = w0;
    uint2 hv0 = *(const uint2*)&g_xhh[(long)n * 128 + lane * 4];
    __half2 q0, q1;
    memcpy(&q0, &hv0.x, 4);
    memcpy(&q1, &hv0.y, 4);
    float2 f0 = __half22float2(q0);
    float2 f1 = __half22float2(q1);
    float4 acc;
    acc.x = w0 * f0.x; acc.y = w0 * f0.y; acc.z = w0 * f1.x; acc.w = w0 * f1.y;

    int cnt = g_cur[n];
    if (cnt > CAP) cnt = CAP;
    const int* bkt = &g_bkt[n * CAP];
#pragma unroll 4
    for (int j = 0; j < cnt; ++j) {
        int s = bkt[j];
        float e = __half2float(__ldg(&g_es[s * 8 + head])) + edn;
        e = (e > 0.f) ? e : 0.2f * e;
        float w = __expf(e);
        uint2 hv = *(const uint2*)&g_xhh[(long)s * 128 + lane * 4];
        __half2 a0, a1;
        memcpy(&a0, &hv.x, 4);
        memcpy(&a1, &hv.y, 4);
        float2 v0 = __half22float2(a0);
        float2 v1 = __half22float2(a1);
        acc.x = fmaf(w, v0.x, acc.x);
        acc.y = fmaf(w, v0.y, acc.y);
        acc.z = fmaf(w, v1.x, acc.z);
        acc.w = fmaf(w, v1.y, acc.w);
        d += w;
    }
    float invd = 1.f / (d + 1e-16f);

    const float4* hin4 = (const float4*)g_h;
    float4 h0 = hin4[n * 32 + lane];
    float4 b4 = ((const float4*)gbias)[lane];
    float4 v;
    v.x = h0.x + acc.x * invd + b4.x;
    v.y = h0.y + acc.y * invd + b4.y;
    v.z = h0.z + acc.z * invd + b4.z;
    v.w = h0.w + acc.w * invd + b4.w;

    float s1 = v.x + v.y + v.z + v.w;
#pragma unroll
    for (int o = 16; o; o >>= 1) s1 += __shfl_xor_sync(0xffffffffu, s1, o);
    float mean = s1 * (1.f / 128.f);
    float cx = v.x - mean, cy = v.y - mean, cz = v.z - mean, cw = v.w - mean;
    float s2 = cx * cx + cy * cy + cz * cz + cw * cw;
#pragma unroll
    for (int o = 16; o; o >>= 1) s2 += __shfl_xor_sync(0xffffffffu, s2, o);
    float rs = rsqrtf(s2 * (1.f / 128.f) + 1e-5f);

    float4 g4 = ((const float4*)lng)[lane];
    float4 lb4 = ((const float4*)lnb)[lane];
    float4 o;
    o.x = fmaf(cx * rs, g4.x, lb4.x);
    o.y = fmaf(cy * rs, g4.y, lb4.y);
    o.z = fmaf(cz * rs, g4.z, lb4.z);
    o.w = fmaf(cw * rs, g4.w, lb4.w);
    ((float4*)hout)[n * 32 + lane] = o;
    if (hh) {
        uint2 u = make_uint2(pack_h2(o.x, o.y), pack_h2(o.z, o.w));
        *(uint2*)&hh[(long)n * 128 + lane * 4] = u;
    }
}

// ---------------- pooling + heads (pool also resets g_cur for next replay) --
__global__ void pool_partial(const float* __restrict__ hf) {
    int gid = blockIdx.x * blockDim.x + threadIdx.x;  // 131072 threads
    if (gid < NN) g_cur[gid] = 0;
    int col = threadIdx.x;
    int b = blockIdx.x;
    int r0 = b * 98;
    int r1 = min(NN, r0 + 98);
    double a = 0.0;
    for (int r = r0; r < r1; ++r) a += (double)hf[(long)r * 128 + col];
    g_part[b * 128 + col] = a;
}

__global__ void head_kernel(const float* __restrict__ Wmu,
                            const float* __restrict__ bmu,
                            const float* __restrict__ Wlv,
                            const float* __restrict__ blv,
                            float* __restrict__ out) {
    __shared__ float p[128];
    int t = threadIdx.x;
    double s = 0.0;
    for (int b = 0; b < 1024; ++b) s += g_part[b * 128 + t];
    float pf = (float)(s / (double)NN);
    p[t] = pf;
    __syncthreads();
    float mu = bmu[t], lv = blv[t];
#pragma unroll 8
    for (int k = 0; k < 128; ++k) {
        float pk = p[k];
        mu = fmaf(pk, Wmu[t * 128 + k], mu);
        lv = fmaf(pk, Wlv[t * 128 + k], lv);
    }
    out[t] = mu;
    out[128 + t] = lv;
    out[256 + (long)NN * 128 + t] = pf;
}

// ---------------- launch -----------------------------------------------------
extern "C" void kernel_launch(void* const* d_in, const int* in_sizes, int n_in,
                              void* d_out, int out_size) {
    const float* x      = (const float*)d_in[0];
    const int*   ei     = (const int*)d_in[1];
    const float* W_in   = (const float*)d_in[2];
    const float* b_in   = (const float*)d_in[3];
    const float* gat_W  = (const float*)d_in[4];
    const float* attsrc = (const float*)d_in[5];
    const float* attdst = (const float*)d_in[6];
    const float* gat_b  = (const float*)d_in[7];
    const float* ln_g   = (const float*)d_in[8];
    const float* ln_b   = (const float*)d_in[9];
    const float* W_mu   = (const float*)d_in[10];
    const float* b_mu   = (const float*)d_in[11];
    const float* W_lv   = (const float*)d_in[12];
    const float* b_lv   = (const float*)d_in[13];
    float* out = (float*)d_out;

    void *p_h, *p_hh, *p_whin, *p_wh;
    cudaGetSymbolAddress(&p_h, g_h);
    cudaGetSymbolAddress(&p_hh, g_hh);
    cudaGetSymbolAddress(&p_whin, g_Whin);
    cudaGetSymbolAddress(&p_wh, g_Wh);
    float* hbuf = (float*)p_h;
    __half* hhbuf = (__half*)p_hh;
    const __half* whinbuf = (const __half*)p_whin;
    const __half* whbuf = (const __half*)p_wh;

    cudaFuncSetAttribute((const void*)gemm_hmma_kernel<256, true, false>,
                         cudaFuncAttributeMaxDynamicSharedMemorySize, HS_TOT);
    cudaFuncSetAttribute((const void*)gemm_hmma_kernel<128, false, true>,
                         cudaFuncAttributeMaxDynamicSharedMemorySize, HS_TOT);

    const int gridtc = (NN + 127) / 128;   // 782

    // profiler captures host-order launch #4 -> layer-0 aggregate.
    prep_kernel<<<2048, 256>>>(W_in, gat_W, ei, ei + EE);               // 1
    gemm_hmma_kernel<256, true, false><<<gridtc, 256, HS_TOT>>>(        // 2
        x, whinbuf, b_in, hbuf, nullptr, nullptr);
    gemm_hmma_kernel<128, false, true><<<gridtc, 256, HS_TOT>>>(        // 3
        hhbuf, whbuf, nullptr, nullptr, attsrc, attdst);
    aggregate_kernel<<<NN / 8, 256>>>(gat_b, ln_g, ln_b, hbuf, hhbuf);  // 4 (profiled)

    for (int l = 1; l < 4; ++l) {
        gemm_hmma_kernel<128, false, true><<<gridtc, 256, HS_TOT>>>(
            hhbuf, whbuf + l * 16384, nullptr, nullptr,
            attsrc + l * 128, attdst + l * 128);
        aggregate_kernel<<<NN / 8, 256>>>(gat_b + l * 128, ln_g + l * 128,
                                          ln_b + l * 128,
                                          (l == 3) ? (out + 256) : hbuf,
                                          (l == 3) ? nullptr : hhbuf);
    }

    pool_partial<<<1024, 128>>>(out + 256);
    head_kernel<<<1, 128>>>(W_mu, b_mu, W_lv, b_lv, out);
}

// round 15
// speedup vs baseline: 1.0177x; 1.0177x over previous
#include <cuda_runtime.h>
#include <cuda_fp16.h>
#include <string.h>
#include <stdint.h>

#define NN 100000
#define EE 1600000
#define DD 128
#define HH 8
#define CAP 96

typedef unsigned long long ull;

// ---------------- scratch (device globals; no allocations allowed) ----------
__device__ __align__(16) float  g_h[NN * DD];    // hidden state fp32 (residual)
__device__ __align__(16) __half g_hh[NN * DD];   // hidden state fp16 (MMA input)
__device__ __align__(16) __half g_xhh[NN * DD];  // transformed feats fp16
__device__ __align__(16) __half g_es[NN * HH];   // src attn logits (fp16)
__device__ __align__(16) __half g_ed[NN * HH];   // dst attn logits (fp16)
__device__ int   g_cur[NN];                      // bucket fill counts (BSS zero)
__device__ int   g_bkt[NN * CAP];                // incoming-src buckets per dst
__device__ double g_part[1024 * DD];
__device__ __align__(16) __half g_Wh[4 * DD * DD];   // gat_W fp16 [l][n][k]

// single dynamic-smem symbol shared by all kernels
extern __shared__ char dynsmem[];

__device__ __forceinline__ uint32_t smem_u32(const void* p) {
    uint32_t a;
    asm("{ .reg .u64 t; cvta.to.shared.u64 t, %1; cvt.u32.u64 %0, t; }"
        : "=r"(a) : "l"(p));
    return a;
}

__device__ __forceinline__ uint32_t pack_h2(float a, float b) {
    __half2 h = __floats2half2_rn(a, b);
    uint32_t u;
    memcpy(&u, &h, 4);
    return u;
}

// ---------------- prep (side stream): gat_W fp16 convert + bucket scatter ----
__global__ void prep_kernel(const float* __restrict__ gw,
                            const int* __restrict__ src,
                            const int* __restrict__ dst) {
    int idx = blockIdx.x * blockDim.x + threadIdx.x;
    if (idx < 65536) {
        g_Wh[idx] = __float2half(gw[idx]);          // [l][n][k] as-is
    } else {
        int stride = gridDim.x * blockDim.x - 65536;
        for (int i = idx - 65536; i < EE; i += stride) {
            int d = dst[i];
            int p = atomicAdd(&g_cur[d], 1);
            if (p < CAP) g_bkt[d * CAP + p] = src[i];
        }
    }
}

// ---------------- unified HMMA GEMM (R12-proven 16x128 warp tile) ------------
// C[M,128] = A[M,K] @ B^T. 128x128 tile/CTA, 8 warps x (16 rows x 128 cols),
// mma.m16n8k16 f16->f32, K chunked by 128.
// AFP32/BFP32: source is fp32, converted to fp16 during swizzled smem store.
#define HS_A 0
#define HS_B 32768
#define HS_AS 65536
#define HS_AD 66048
#define HS_TOT 66560

__device__ __forceinline__ void ldsm_x4(uint32_t& r0, uint32_t& r1,
                                        uint32_t& r2, uint32_t& r3,
                                        uint32_t addr) {
    asm volatile(
        "ldmatrix.sync.aligned.m8n8.x4.shared.b16 {%0,%1,%2,%3}, [%4];"
        : "=r"(r0), "=r"(r1), "=r"(r2), "=r"(r3) : "r"(addr));
}

__device__ __forceinline__ void mma16816(float* c, uint32_t a0, uint32_t a1,
                                         uint32_t a2, uint32_t a3,
                                         uint32_t b0, uint32_t b1) {
    asm volatile(
        "mma.sync.aligned.m16n8k16.row.col.f32.f16.f16.f32 "
        "{%0,%1,%2,%3}, {%4,%5,%6,%7}, {%8,%9}, {%0,%1,%2,%3};"
        : "+f"(c[0]), "+f"(c[1]), "+f"(c[2]), "+f"(c[3])
        : "r"(a0), "r"(a1), "r"(a2), "r"(a3), "r"(b0), "r"(b1));
}

__device__ __forceinline__ uint4 cvt_f32x8_to_h8(const float* p) {
    float4 f0 = *(const float4*)p;
    float4 f1 = *(const float4*)(p + 4);
    return make_uint4(pack_h2(f0.x, f0.y), pack_h2(f0.z, f0.w),
                      pack_h2(f1.x, f1.y), pack_h2(f1.z, f1.w));
}

template <int K, bool AFP32, bool BFP32, bool ATTN>
__global__ void __launch_bounds__(256, 2)
gemm_hmma_kernel(const void* __restrict__ Asrc, const void* __restrict__ Bsrc,
                 const float* __restrict__ bias, float* __restrict__ Cout,
                 const float* __restrict__ asrc, const float* __restrict__ adst) {
    char* smem = dynsmem;
    uint32_t sb = smem_u32(smem);
    int tid = threadIdx.x;
    int lane = tid & 31;
    int wid = tid >> 5;
    long row0 = (long)blockIdx.x * 128;

    int m0 = wid * 16;
    float acc[16][4];
#pragma unroll
    for (int t = 0; t < 16; ++t)
#pragma unroll
        for (int i = 0; i < 4; ++i) acc[t][i] = 0.f;

    int l15 = lane & 15;
    int khalf = lane >> 4;
    int ar = m0 + l15;

    for (int kk = 0; kk < K; kk += 128) {
        if (kk) __syncthreads();
#pragma unroll
        for (int p = 0; p < 8; ++p) {
            int lin = p * 256 + tid;       // 0..2047 chunks
            int r = lin >> 4;              // row 0..127
            int c = lin & 15;              // 16B chunk 0..15
            int swc = c ^ (r & 7);
            long grow = row0 + r;
            uint4 va = make_uint4(0, 0, 0, 0);
            if (grow < NN) {
                if (AFP32)
                    va = cvt_f32x8_to_h8((const float*)Asrc + grow * K + kk + c * 8);
                else
                    va = *(const uint4*)((const __half*)Asrc + grow * 128 + c * 8);
            }
            *(uint4*)(smem + HS_A + r * 256 + swc * 16) = va;
            uint4 vb;
            if (BFP32)
                vb = cvt_f32x8_to_h8((const float*)Bsrc + (long)r * K + kk + c * 8);
            else
                vb = *(const uint4*)&((const __half*)Bsrc)[(long)r * K + kk + c * 8];
            *(uint4*)(smem + HS_B + r * 256 + swc * 16) = vb;
        }
        if (kk == 0 && tid < 128) {
            if (ATTN) {
                ((float*)(smem + HS_AS))[tid] = asrc[tid];
                ((float*)(smem + HS_AD))[tid] = adst[tid];
            }
            if (AFP32) ((float*)(smem + HS_AS))[tid] = bias[tid];
        }
        __syncthreads();

#pragma unroll
        for (int ks = 0; ks < 8; ++ks) {
            int kc = ks * 2 + khalf;
            uint32_t a0, a1, a2, a3;
            ldsm_x4(a0, a1, a2, a3,
                    sb + HS_A + ar * 256 + (kc ^ (ar & 7)) * 16);
#pragma unroll
            for (int j = 0; j < 8; ++j) {
                int br = j * 16 + l15;
                uint32_t b0, b1, b2, b3;
                ldsm_x4(b0, b1, b2, b3,
                        sb + HS_B + br * 256 + (kc ^ (br & 7)) * 16);
                mma16816(acc[2 * j], a0, a1, a2, a3, b0, b2);
                mma16816(acc[2 * j + 1], a0, a1, a2, a3, b1, b3);
            }
        }
    }

    // epilogue
    int rlo = m0 + (lane >> 2);
    long glo = row0 + rlo;
    long ghi = glo + 8;
    bool vlo = (glo < NN), vhi = (ghi < NN);

    if (AFP32) {
        const float* sbias = (const float*)(smem + HS_AS);
#pragma unroll
        for (int t = 0; t < 16; ++t) {
            int col = t * 8 + (lane & 3) * 2;
            float b0 = sbias[col], b1 = sbias[col + 1];
            float c0 = acc[t][0] + b0, c1 = acc[t][1] + b1;
            float c2 = acc[t][2] + b0, c3 = acc[t][3] + b1;
            if (vlo) {
                *(float2*)&Cout[glo * 128 + col] = make_float2(c0, c1);
                *(__half2*)&g_hh[glo * 128 + col] = __floats2half2_rn(c0, c1);
            }
            if (vhi) {
                *(float2*)&Cout[ghi * 128 + col] = make_float2(c2, c3);
                *(__half2*)&g_hh[ghi * 128 + col] = __floats2half2_rn(c2, c3);
            }
        }
    }
    if (ATTN) {
        const float* s_as = (const float*)(smem + HS_AS);
        const float* s_ad = (const float*)(smem + HS_AD);
        float eslo[8], edlo[8], eshi[8], edhi[8];
#pragma unroll
        for (int h = 0; h < 8; ++h) { eslo[h] = edlo[h] = eshi[h] = edhi[h] = 0.f; }
#pragma unroll
        for (int t = 0; t < 16; ++t) {
            int col = t * 8 + (lane & 3) * 2;
            int h = t >> 1;
            float c0 = acc[t][0], c1 = acc[t][1];
            float c2 = acc[t][2], c3 = acc[t][3];
            if (vlo) *(__half2*)&g_xhh[glo * 128 + col] = __floats2half2_rn(c0, c1);
            if (vhi) *(__half2*)&g_xhh[ghi * 128 + col] = __floats2half2_rn(c2, c3);
            float as0 = s_as[col], as1 = s_as[col + 1];
            float ad0 = s_ad[col], ad1 = s_ad[col + 1];
            eslo[h] += c0 * as0 + c1 * as1;
            edlo[h] += c0 * ad0 + c1 * ad1;
            eshi[h] += c2 * as0 + c3 * as1;
            edhi[h] += c2 * ad0 + c3 * ad1;
        }
#pragma unroll
        for (int h = 0; h < 8; ++h) {
            eslo[h] += __shfl_xor_sync(0xffffffffu, eslo[h], 1);
            eslo[h] += __shfl_xor_sync(0xffffffffu, eslo[h], 2);
            edlo[h] += __shfl_xor_sync(0xffffffffu, edlo[h], 1);
            edlo[h] += __shfl_xor_sync(0xffffffffu, edlo[h], 2);
            eshi[h] += __shfl_xor_sync(0xffffffffu, eshi[h], 1);
            eshi[h] += __shfl_xor_sync(0xffffffffu, eshi[h], 2);
            edhi[h] += __shfl_xor_sync(0xffffffffu, edhi[h], 1);
            edhi[h] += __shfl_xor_sync(0xffffffffu, edhi[h], 2);
        }
        if ((lane & 3) == 0) {
            if (vlo) {
                *(uint4*)&g_es[glo * 8] =
                    make_uint4(pack_h2(eslo[0], eslo[1]), pack_h2(eslo[2], eslo[3]),
                               pack_h2(eslo[4], eslo[5]), pack_h2(eslo[6], eslo[7]));
                *(uint4*)&g_ed[glo * 8] =
                    make_uint4(pack_h2(edlo[0], edlo[1]), pack_h2(edlo[2], edlo[3]),
                               pack_h2(edlo[4], edlo[5]), pack_h2(edlo[6], edlo[7]));
            }
            if (vhi) {
                *(uint4*)&g_es[ghi * 8] =
                    make_uint4(pack_h2(eshi[0], eshi[1]), pack_h2(eshi[2], eshi[3]),
                               pack_h2(eshi[4], eshi[5]), pack_h2(eshi[6], eshi[7]));
                *(uint4*)&g_ed[ghi * 8] =
                    make_uint4(pack_h2(edhi[0], edhi[1]), pack_h2(edhi[2], edhi[3]),
                               pack_h2(edhi[4], edhi[5]), pack_h2(edhi[6], edhi[7]));
            }
        }
    }
}

// ---------------- fused aggregate + residual + LayerNorm --------------------
// One warp per node; lane owns 8 fp16 channels (one LDG.128). The two
// half-warps process 2 edges per iteration (half h takes edges j+h), so the
// scalar weight chain is amortized over 2 edges. acc halves folded by one
// shfl_xor(16); denominator likewise (self-loop counted in half 0 only).
__device__ __forceinline__ void cvt8(uint4 u, float* f) {
    __half2 a, b, c, d;
    memcpy(&a, &u.x, 4);
    memcpy(&b, &u.y, 4);
    memcpy(&c, &u.z, 4);
    memcpy(&d, &u.w, 4);
    float2 p = __half22float2(a), q = __half22float2(b);
    float2 r = __half22float2(c), s = __half22float2(d);
    f[0] = p.x; f[1] = p.y; f[2] = q.x; f[3] = q.y;
    f[4] = r.x; f[5] = r.y; f[6] = s.x; f[7] = s.y;
}

__global__ void __launch_bounds__(256)
aggregate_kernel(const float* __restrict__ gbias, const float* __restrict__ lng,
                 const float* __restrict__ lnb, float* __restrict__ hout,
                 __half* __restrict__ hh) {
    int lane = threadIdx.x & 31;
    int n = blockIdx.x * 8 + (threadIdx.x >> 5);
    int l15 = lane & 15;
    int half = lane >> 4;
    int head = l15 >> 1;              // channels [8*l15, 8*l15+8) c head

    float edn = __half2float(g_ed[n * 8 + head]);
    float e0 = __half2float(g_es[n * 8 + head]) + edn;
    e0 = fmaxf(e0, 0.2f * e0);
    float w0 = (half == 0) ? __expf(e0) : 0.f;   // self-loop only in half 0

    const uint4* xh4 = (const uint4*)g_xhh;      // 16 uint4 per row
    uint4 hv0 = xh4[(long)n * 16 + l15];
    float f0[8];
    cvt8(hv0, f0);
    float acc[8];
#pragma unroll
    for (int c = 0; c < 8; ++c) acc[c] = w0 * f0[c];
    float dpart = w0;

    int cnt = g_cur[n];
    if (cnt > CAP) cnt = CAP;
    const int* bkt = &g_bkt[n * CAP];
    for (int j = half; j < cnt; j += 2) {
        int s = bkt[j];
        float e = __half2float(__ldg(&g_es[s * 8 + head])) + edn;
        e = fmaxf(e, 0.2f * e);
        float w = __expf(e);
        dpart += w;
        uint4 hv = __ldg(&xh4[(long)s * 16 + l15]);
        float v[8];
        cvt8(hv, v);
#pragma unroll
        for (int c = 0; c < 8; ++c) acc[c] = fmaf(w, v[c], acc[c]);
    }

    // fold the two half-warps
#pragma unroll
    for (int c = 0; c < 8; ++c) acc[c] += __shfl_xor_sync(0xffffffffu, acc[c], 16);
    float d = dpart + __shfl_xor_sync(0xffffffffu, dpart, 16);
    float invd = 1.f / (d + 1e-16f);

    const float4* hin4 = (const float4*)g_h;
    float4 ha = hin4[n * 32 + l15 * 2];
    float4 hb = hin4[n * 32 + l15 * 2 + 1];
    float4 ba = ((const float4*)gbias)[l15 * 2];
    float4 bb = ((const float4*)gbias)[l15 * 2 + 1];
    float v[8];
    v[0] = ha.x + acc[0] * invd + ba.x;
    v[1] = ha.y + acc[1] * invd + ba.y;
    v[2] = ha.z + acc[2] * invd + ba.z;
    v[3] = ha.w + acc[3] * invd + ba.w;
    v[4] = hb.x + acc[4] * invd + bb.x;
    v[5] = hb.y + acc[5] * invd + bb.y;
    v[6] = hb.z + acc[6] * invd + bb.z;
    v[7] = hb.w + acc[7] * invd + bb.w;

    // LayerNorm: both halves hold identical copies -> reduce over 32 lanes /256
    float s1 = 0.f;
#pragma unroll
    for (int c = 0; c < 8; ++c) s1 += v[c];
#pragma unroll
    for (int o = 16; o; o >>= 1) s1 += __shfl_xor_sync(0xffffffffu, s1, o);
    float mean = s1 * (1.f / 256.f);
    float cx[8], s2 = 0.f;
#pragma unroll
    for (int c = 0; c < 8; ++c) { cx[c] = v[c] - mean; s2 += cx[c] * cx[c]; }
#pragma unroll
    for (int o = 16; o; o >>= 1) s2 += __shfl_xor_sync(0xffffffffu, s2, o);
    float rs = rsqrtf(s2 * (1.f / 256.f) + 1e-5f);

    float4 ga = ((const float4*)lng)[l15 * 2];
    float4 gb = ((const float4*)lng)[l15 * 2 + 1];
    float4 la = ((const float4*)lnb)[l15 * 2];
    float4 lb = ((const float4*)lnb)[l15 * 2 + 1];
    float o_[8];
    o_[0] = fmaf(cx[0] * rs, ga.x, la.x);
    o_[1] = fmaf(cx[1] * rs, ga.y, la.y);
    o_[2] = fmaf(cx[2] * rs, ga.z, la.z);
    o_[3] = fmaf(cx[3] * rs, ga.w, la.w);
    o_[4] = fmaf(cx[4] * rs, gb.x, lb.x);
    o_[5] = fmaf(cx[5] * rs, gb.y, lb.y);
    o_[6] = fmaf(cx[6] * rs, gb.z, lb.z);
    o_[7] = fmaf(cx[7] * rs, gb.w, lb.w);

    if (half == 0) {
        float4* out4 = (float4*)hout;
        out4[n * 32 + l15 * 2] = make_float4(o_[0], o_[1], o_[2], o_[3]);
        out4[n * 32 + l15 * 2 + 1] = make_float4(o_[4], o_[5], o_[6], o_[7]);
        if (hh) {
            *(uint4*)&hh[(long)n * 128 + l15 * 8] =
                make_uint4(pack_h2(o_[0], o_[1]), pack_h2(o_[2], o_[3]),
                           pack_h2(o_[4], o_[5]), pack_h2(o_[6], o_[7]));
        }
    }
}

// ---------------- pooling + heads (pool also resets g_cur for next replay) --
__global__ void pool_partial(const float* __restrict__ hf) {
    int gid = blockIdx.x * blockDim.x + threadIdx.x;  // 131072 threads
    if (gid < NN) g_cur[gid] = 0;
    int col = threadIdx.x;
    int b = blockIdx.x;
    int r0 = b * 98;
    int r1 = min(NN, r0 + 98);
    double a = 0.0;
    for (int r = r0; r < r1; ++r) a += (double)hf[(long)r * 128 + col];
    g_part[b * 128 + col] = a;
}

__global__ void head_kernel(const float* __restrict__ Wmu,
                            const float* __restrict__ bmu,
                            const float* __restrict__ Wlv,
                            const float* __restrict__ blv,
                            float* __restrict__ out) {
    __shared__ float p[128];
    int t = threadIdx.x;
    double s = 0.0;
    for (int b = 0; b < 1024; ++b) s += g_part[b * 128 + t];
    float pf = (float)(s / (double)NN);
    p[t] = pf;
    __syncthreads();
    float mu = bmu[t], lv = blv[t];
#pragma unroll 8
    for (int k = 0; k < 128; ++k) {
        float pk = p[k];
        mu = fmaf(pk, Wmu[t * 128 + k], mu);
        lv = fmaf(pk, Wlv[t * 128 + k], lv);
    }
    out[t] = mu;
    out[128 + t] = lv;
    out[256 + (long)NN * 128 + t] = pf;
}

// ---------------- launch -----------------------------------------------------
extern "C" void kernel_launch(void* const* d_in, const int* in_sizes, int n_in,
                              void* d_out, int out_size) {
    const float* x      = (const float*)d_in[0];
    const int*   ei     = (const int*)d_in[1];
    const float* W_in   = (const float*)d_in[2];
    const float* b_in   = (const float*)d_in[3];
    const float* gat_W  = (const float*)d_in[4];
    const float* attsrc = (const float*)d_in[5];
    const float* attdst = (const float*)d_in[6];
    const float* gat_b  = (const float*)d_in[7];
    const float* ln_g   = (const float*)d_in[8];
    const float* ln_b   = (const float*)d_in[9];
    const float* W_mu   = (const float*)d_in[10];
    const float* b_mu   = (const float*)d_in[11];
    const float* W_lv   = (const float*)d_in[12];
    const float* b_lv   = (const float*)d_in[13];
    float* out = (float*)d_out;

    void *p_h, *p_hh, *p_wh;
    cudaGetSymbolAddress(&p_h, g_h);
    cudaGetSymbolAddress(&p_hh, g_hh);
    cudaGetSymbolAddress(&p_wh, g_Wh);
    float* hbuf = (float*)p_h;
    __half* hhbuf = (__half*)p_hh;
    const __half* whbuf = (const __half*)p_wh;

    cudaFuncSetAttribute((const void*)gemm_hmma_kernel<256, true, true, false>,
                         cudaFuncAttributeMaxDynamicSharedMemorySize, HS_TOT);
    cudaFuncSetAttribute((const void*)gemm_hmma_kernel<128, false, false, true>,
                         cudaFuncAttributeMaxDynamicSharedMemorySize, HS_TOT);

    const int gridtc = (NN + 127) / 128;   // 782

    // fork: prep (layer-weight convert + bucket scatter) runs on s2
    // concurrently with gemm256 (which converts W_in in-flight).
    cudaStream_t s2;
    cudaStreamCreateWithFlags(&s2, cudaStreamNonBlocking);
    cudaEvent_t ev0, ev1;
    cudaEventCreateWithFlags(&ev0, cudaEventDisableTiming);
    cudaEventCreateWithFlags(&ev1, cudaEventDisableTiming);

    cudaEventRecord(ev0, 0);
    cudaStreamWaitEvent(s2, ev0, 0);
    prep_kernel<<<2048, 256, 0, s2>>>(gat_W, ei, ei + EE);              // 1
    cudaEventRecord(ev1, s2);

    gemm_hmma_kernel<256, true, true, false><<<gridtc, 256, HS_TOT>>>(  // 2
        x, W_in, b_in, hbuf, nullptr, nullptr);

    cudaStreamWaitEvent(0, ev1, 0);   // join: gemm_l0 needs g_Wh, agg needs buckets

    gemm_hmma_kernel<128, false, false, true><<<gridtc, 256, HS_TOT>>>( // 3
        hhbuf, whbuf, nullptr, nullptr, attsrc, attdst);
    aggregate_kernel<<<NN / 8, 256>>>(gat_b, ln_g, ln_b, hbuf, hhbuf);  // 4 (profiled)

    for (int l = 1; l < 4; ++l) {
        gemm_hmma_kernel<128, false, false, true><<<gridtc, 256, HS_TOT>>>(
            hhbuf, whbuf + l * 16384, nullptr, nullptr,
            attsrc + l * 128, attdst + l * 128);
        aggregate_kernel<<<NN / 8, 256>>>(gat_b + l * 128, ln_g + l * 128,
                                          ln_b + l * 128,
                                          (l == 3) ? (out + 256) : hbuf,
                                          (l == 3) ? nullptr : hhbuf);
    }

    pool_partial<<<1024, 128>>>(out + 256);
    head_kernel<<<1, 128>>>(W_mu, b_mu, W_lv, b_lv, out);
}